// round 7
// baseline (speedup 1.0000x reference)
#include <cuda_runtime.h>
#include <cuda_bf16.h>
#include <cstdint>

// Embedding gather: out[row, :] = w[x[row], :]
// x: [16384] int32, w: [50257, 1024] fp32, out: [16384, 1024] fp32
//
// Working-set insight: unique gathered w rows (~57 MB) + out (64 MB) = ~121 MB,
// which FITS in GB300's ~126 MB L2. The graph-timing loop replays the same x,
// so both streams have perfect cross-iteration reuse. Pin both with
// L2::evict_last; steady-state DRAM traffic should approach zero and the
// kernel becomes L2-bandwidth-bound.
//
// 8 rows per block, 256 threads, MLP=8 front-batched LDG.128.

#define EMB_DIM 1024
#define VEC_PER_ROW (EMB_DIM / 4)   // 256 float4 per row
#define ROWS_PER_BLOCK 8

__device__ __forceinline__ float4 ldg_el(const float4* p, uint64_t pol) {
    float4 v;
    asm volatile("ld.global.nc.L2::cache_hint.v4.f32 {%0,%1,%2,%3}, [%4], %5;"
                 : "=f"(v.x), "=f"(v.y), "=f"(v.z), "=f"(v.w)
                 : "l"(p), "l"(pol));
    return v;
}

__device__ __forceinline__ void stg_el(float4* p, float4 v, uint64_t pol) {
    asm volatile("st.global.L2::cache_hint.v4.f32 [%0], {%1,%2,%3,%4}, %5;"
                 :: "l"(p), "f"(v.x), "f"(v.y), "f"(v.z), "f"(v.w), "l"(pol)
                 : "memory");
}

__global__ void __launch_bounds__(256) embedding_gather_kernel(
    const int* __restrict__ x,
    const float4* __restrict__ w,
    float4* __restrict__ out,
    int n_rows)
{
    uint64_t pol;
    asm("createpolicy.fractional.L2::evict_last.b64 %0, 1.0;" : "=l"(pol));

    int row0 = blockIdx.x * ROWS_PER_BLOCK;
    int c = threadIdx.x;                       // column slot 0..255

    // Uniform index loads: 8 ints as two int4 (32B-aligned since row0%8==0)
    int4 ia = __ldg((const int4*)(x + row0));
    int4 ib = __ldg((const int4*)(x + row0 + 4));

    const float4* base = w + c;

    // Front-batched independent gathers: MLP = 8, evict-last (hot rows are
    // re-read every graph replay -> keep resident in L2)
    float4 v0 = ldg_el(base + (size_t)ia.x * VEC_PER_ROW, pol);
    float4 v1 = ldg_el(base + (size_t)ia.y * VEC_PER_ROW, pol);
    float4 v2 = ldg_el(base + (size_t)ia.z * VEC_PER_ROW, pol);
    float4 v3 = ldg_el(base + (size_t)ia.w * VEC_PER_ROW, pol);
    float4 v4 = ldg_el(base + (size_t)ib.x * VEC_PER_ROW, pol);
    float4 v5 = ldg_el(base + (size_t)ib.y * VEC_PER_ROW, pol);
    float4 v6 = ldg_el(base + (size_t)ib.z * VEC_PER_ROW, pol);
    float4 v7 = ldg_el(base + (size_t)ib.w * VEC_PER_ROW, pol);

    float4* dst = out + (size_t)row0 * VEC_PER_ROW + c;
    stg_el(dst + 0 * VEC_PER_ROW, v0, pol);
    stg_el(dst + 1 * VEC_PER_ROW, v1, pol);
    stg_el(dst + 2 * VEC_PER_ROW, v2, pol);
    stg_el(dst + 3 * VEC_PER_ROW, v3, pol);
    stg_el(dst + 4 * VEC_PER_ROW, v4, pol);
    stg_el(dst + 5 * VEC_PER_ROW, v5, pol);
    stg_el(dst + 6 * VEC_PER_ROW, v6, pol);
    stg_el(dst + 7 * VEC_PER_ROW, v7, pol);
}

extern "C" void kernel_launch(void* const* d_in, const int* in_sizes, int n_in,
                              void* d_out, int out_size) {
    const int*    x = (const int*)d_in[0];          // [16384] indices
    const float4* w = (const float4*)d_in[1];       // [50257*1024] fp32 as float4
    float4*       o = (float4*)d_out;

    int n_rows = in_sizes[0];                       // 16384
    int n_blocks = n_rows / ROWS_PER_BLOCK;         // 2048
    embedding_gather_kernel<<<n_blocks, 256>>>(x, w, o, n_rows);
}

// round 8
// speedup vs baseline: 1.2600x; 1.2600x over previous
#include <cuda_runtime.h>
#include <cuda_bf16.h>
#include <cstdint>

// Embedding gather: out[row, :] = w[x[row], :]
// x: [16384] int32, w: [50257, 1024] fp32, out: [16384, 1024] fp32
//
// Steady-state strategy (graph replay loop, same x every iteration):
//   - hot gathered w rows (~14K unique rows = ~57 MB) -> keep resident in L2
//     (ld.global.nc + L2::evict_last hint)
//   - out writes (64 MB, zero reuse) -> st.global.cs streaming stores so they
//     do NOT displace the hot read set from L2.
// Harness-measured: .cs stores are worth ~5 us vs letting out occupy L2.
//
// 4 rows per block, 256 threads, front-batched MLP=4 gather LDG.128.

#define EMB_DIM 1024
#define VEC_PER_ROW (EMB_DIM / 4)   // 256 float4 per row
#define ROWS_PER_BLOCK 4

__device__ __forceinline__ float4 ldg_el(const float4* p, uint64_t pol) {
    float4 v;
    asm volatile("ld.global.nc.L2::cache_hint.v4.f32 {%0,%1,%2,%3}, [%4], %5;"
                 : "=f"(v.x), "=f"(v.y), "=f"(v.z), "=f"(v.w)
                 : "l"(p), "l"(pol));
    return v;
}

__device__ __forceinline__ void stcs_f4(float4* p, float4 v) {
    asm volatile("st.global.cs.v4.f32 [%0], {%1,%2,%3,%4};"
                 :: "l"(p), "f"(v.x), "f"(v.y), "f"(v.z), "f"(v.w) : "memory");
}

__global__ void __launch_bounds__(256, 8) embedding_gather_kernel(
    const int* __restrict__ x,
    const float4* __restrict__ w,
    float4* __restrict__ out,
    int n_rows)
{
    uint64_t pol;
    asm("createpolicy.fractional.L2::evict_last.b64 %0, 1.0;" : "=l"(pol));

    int row0 = blockIdx.x * ROWS_PER_BLOCK;
    int c = threadIdx.x;                       // column slot 0..255

    // Uniform index load: 4 ints as one int4 (16B-aligned since row0%4==0)
    int4 ia = __ldg((const int4*)(x + row0));

    const float4* base = w + c;

    // Front-batched independent gathers: MLP = 4, pinned in L2 (evict_last)
    float4 v0 = ldg_el(base + (size_t)ia.x * VEC_PER_ROW, pol);
    float4 v1 = ldg_el(base + (size_t)ia.y * VEC_PER_ROW, pol);
    float4 v2 = ldg_el(base + (size_t)ia.z * VEC_PER_ROW, pol);
    float4 v3 = ldg_el(base + (size_t)ia.w * VEC_PER_ROW, pol);

    // Streaming stores: keep the write stream OUT of L2
    float4* dst = out + (size_t)row0 * VEC_PER_ROW + c;
    stcs_f4(dst + 0 * VEC_PER_ROW, v0);
    stcs_f4(dst + 1 * VEC_PER_ROW, v1);
    stcs_f4(dst + 2 * VEC_PER_ROW, v2);
    stcs_f4(dst + 3 * VEC_PER_ROW, v3);
}

extern "C" void kernel_launch(void* const* d_in, const int* in_sizes, int n_in,
                              void* d_out, int out_size) {
    const int*    x = (const int*)d_in[0];          // [16384] indices
    const float4* w = (const float4*)d_in[1];       // [50257*1024] fp32 as float4
    float4*       o = (float4*)d_out;

    int n_rows = in_sizes[0];                       // 16384
    int n_blocks = n_rows / ROWS_PER_BLOCK;         // 4096
    embedding_gather_kernel<<<n_blocks, 256>>>(x, w, o, n_rows);
}